// round 13
// baseline (speedup 1.0000x reference)
#include <cuda_runtime.h>
#include <cstdint>

#define NB    2
#define N1V   4096
#define N2V   16384
#define CINV  512
#define CSKV  256
#define COUTV 256

#define AS_STRIDE 72    // words; (8*tg+g)%32 distinct -> conflict-free frags
#define BS_STRIDE 136
#define AS_BUF_BYTES (16 * AS_STRIDE * 4)   // 4608
#define BS_BUF_BYTES (16 * BS_STRIDE * 4)   // 8704
#define PIPE_BYTES   (2 * AS_BUF_BYTES + 2 * BS_BUF_BYTES)  // 26624

// Scratch: h1 transposed [b][n1][co], knn idx/weights, tf32 weights WT[k][co].
__device__ float g_h1T[(size_t)NB * N1V * COUTV];
__device__ int   g_idx[NB * N2V * 3];
__device__ float g_wgt[NB * N2V * 3];
__device__ float g_WT1[CINV * COUTV];
__device__ float g_WT2[CSKV * COUTV];

// ---------------- helpers ----------------
__device__ __forceinline__ uint32_t s2u(const void* p) {
    return (uint32_t)__cvta_generic_to_shared(p);
}
__device__ __forceinline__ void cpa16(uint32_t dst, const void* src) {
    asm volatile("cp.async.cg.shared.global [%0], [%1], 16;\n" :: "r"(dst), "l"(src));
}
__device__ __forceinline__ void cpa_commit() {
    asm volatile("cp.async.commit_group;\n");
}
__device__ __forceinline__ void cpa_wait1() {
    asm volatile("cp.async.wait_group 1;\n");
}
__device__ __forceinline__ void cpa_wait0() {
    asm volatile("cp.async.wait_group 0;\n");
}
__device__ __forceinline__ uint32_t f2tf32(float x) {
    uint32_t u;
    asm("cvt.rna.tf32.f32 %0, %1;" : "=r"(u) : "f"(x));
    return u;
}
__device__ __forceinline__ void mma_tf32(float* c, const uint32_t* a,
                                         uint32_t b0, uint32_t b1) {
    asm volatile(
        "mma.sync.aligned.m16n8k8.row.col.f32.tf32.tf32.f32 "
        "{%0,%1,%2,%3}, {%4,%5,%6,%7}, {%8,%9}, {%0,%1,%2,%3};\n"
        : "+f"(c[0]), "+f"(c[1]), "+f"(c[2]), "+f"(c[3])
        : "r"(a[0]), "r"(a[1]), "r"(a[2]), "r"(a[3]), "r"(b0), "r"(b1));
}

// ===========================================================================
// Prologue: WT[k][co] = tf32_round( W[co][k] * bn_scale[co] )
// ===========================================================================
__global__ __launch_bounds__(256)
void wtrans_kernel(const float* __restrict__ W1, const float* __restrict__ g1,
                   const float* __restrict__ v1,
                   const float* __restrict__ W2, const float* __restrict__ g2,
                   const float* __restrict__ v2)
{
    __shared__ float tile[32][33];
    const int which = blockIdx.z;
    const int Cin   = which ? CSKV : CINV;
    if (blockIdx.y * 32 >= Cin) return;
    const float* W  = which ? W2 : W1;
    const float* g  = which ? g2 : g1;
    const float* v  = which ? v2 : v1;
    float* WT       = which ? g_WT2 : g_WT1;

    const int co0 = blockIdx.x * 32;
    const int k0  = blockIdx.y * 32;
    const int lx  = threadIdx.x & 31;
    const int ly  = threadIdx.x >> 5;

    #pragma unroll
    for (int r = 0; r < 4; r++)
        tile[ly + r * 8][lx] = W[(size_t)(co0 + ly + r * 8) * Cin + k0 + lx];
    __syncthreads();

    const float sc = g[co0 + lx] * rsqrtf(v[co0 + lx] + 1e-5f);
    #pragma unroll
    for (int r = 0; r < 4; r++)
        WT[(size_t)(k0 + ly + r * 8) * COUTV + co0 + lx] =
            __uint_as_float(f2tf32(tile[lx][ly + r * 8] * sc));
}

// ===========================================================================
// tf32 MMA mainloop: tile 64co x 128n x 16k, 128 thr (4 warps, 2co x 2n),
// warp tile 32co x 64n (2 x 8 m16n8k8 frags). Double-buffered cp.async.
// acc[2][8][4]; thread element map:
//   co = cw + cf*16 + g + (e>=2? 8:0),  n = nw + nf*8 + 2*tg + (e&1)
// ===========================================================================
#define MMA_MAINLOOP(WTSRC, XB, NSTRIDE, NCHUNKS)                                \
    const int a_row = t >> 4, a_c4 = (t & 15) * 4;                               \
    const uint32_t sA0 = s2u(AsB) + (uint32_t)(a_row * AS_STRIDE + a_c4) * 4u;   \
    const uint32_t sA1 = s2u(AsB) + (uint32_t)((a_row + 8) * AS_STRIDE + a_c4) * 4u; \
    const int b_col = (t & 31) * 4;                                              \
    const int b_rw  = t >> 5;                                                    \
    uint32_t sB[4];                                                              \
    _Pragma("unroll")                                                            \
    for (int r = 0; r < 4; r++)                                                  \
        sB[r] = s2u(BsB) + (uint32_t)((b_rw + r * 4) * BS_STRIDE + b_col) * 4u;  \
    float acc[2][8][4];                                                          \
    _Pragma("unroll")                                                            \
    for (int cf = 0; cf < 2; cf++)                                               \
        _Pragma("unroll")                                                        \
        for (int nf = 0; nf < 8; nf++)                                           \
            _Pragma("unroll")                                                    \
            for (int e = 0; e < 4; e++) acc[cf][nf][e] = 0.f;                    \
    cpa16(sA0, &WTSRC[(size_t)a_row * COUTV + co0 + a_c4]);                      \
    cpa16(sA1, &WTSRC[(size_t)(a_row + 8) * COUTV + co0 + a_c4]);                \
    _Pragma("unroll")                                                            \
    for (int r = 0; r < 4; r++)                                                  \
        cpa16(sB[r], &XB[(size_t)(b_rw + r * 4) * NSTRIDE + n0 + b_col]);        \
    cpa_commit();                                                                \
    for (int ch = 0; ch < NCHUNKS; ch++) {                                       \
        const int cur = ch & 1;                                                  \
        if (ch + 1 < NCHUNKS) {                                                  \
            const int nxt = cur ^ 1;                                             \
            const int k0n = (ch + 1) * 16;                                       \
            cpa16(sA0 + nxt * AS_BUF_BYTES,                                      \
                  &WTSRC[(size_t)(k0n + a_row) * COUTV + co0 + a_c4]);           \
            cpa16(sA1 + nxt * AS_BUF_BYTES,                                      \
                  &WTSRC[(size_t)(k0n + a_row + 8) * COUTV + co0 + a_c4]);       \
            _Pragma("unroll")                                                    \
            for (int r = 0; r < 4; r++)                                          \
                cpa16(sB[r] + nxt * BS_BUF_BYTES,                                \
                      &XB[(size_t)(k0n + b_rw + r * 4) * NSTRIDE + n0 + b_col]); \
            cpa_commit();                                                        \
            cpa_wait1();                                                         \
        } else {                                                                 \
            cpa_wait0();                                                         \
        }                                                                        \
        __syncthreads();                                                         \
        const float* Ab = AsB + cur * (16 * AS_STRIDE);                          \
        const float* Bb = BsB + cur * (16 * BS_STRIDE);                          \
        _Pragma("unroll")                                                        \
        for (int s = 0; s < 2; s++) {                                            \
            const int kr0 = s * 8 + tg;                                          \
            uint32_t af[2][4];                                                   \
            _Pragma("unroll")                                                    \
            for (int cf = 0; cf < 2; cf++) {                                     \
                const int cb = cw + cf * 16 + g;                                 \
                af[cf][0] = __float_as_uint(Ab[kr0 * AS_STRIDE + cb]);           \
                af[cf][1] = __float_as_uint(Ab[kr0 * AS_STRIDE + cb + 8]);       \
                af[cf][2] = __float_as_uint(Ab[(kr0 + 4) * AS_STRIDE + cb]);     \
                af[cf][3] = __float_as_uint(Ab[(kr0 + 4) * AS_STRIDE + cb + 8]); \
            }                                                                    \
            _Pragma("unroll")                                                    \
            for (int nf = 0; nf < 8; nf++) {                                     \
                const int nn = nw + nf * 8 + g;                                  \
                uint32_t b0 = f2tf32(Bb[kr0 * BS_STRIDE + nn]);                  \
                uint32_t b1 = f2tf32(Bb[(kr0 + 4) * BS_STRIDE + nn]);            \
                mma_tf32(acc[0][nf], af[0], b0, b1);                             \
                mma_tf32(acc[1][nf], af[1], b0, b1);                             \
            }                                                                    \
        }                                                                        \
        __syncthreads();                                                         \
    }

// ---------------------------------------------------------------------------
// Fused front kernel: blocks [0,256) conv1 (tf32 MMA), blocks [256,512) 3-NN.
// ---------------------------------------------------------------------------
__global__ __launch_bounds__(128, 4)
void front_kernel(const float* __restrict__ x1,
                  const float* __restrict__ b1, const float* __restrict__ m1,
                  const float* __restrict__ g1, const float* __restrict__ v1,
                  const float* __restrict__ p1, const float* __restrict__ p2)
{
    extern __shared__ char SRAW[];
    const int t   = threadIdx.x;
    const int bid = blockIdx.x;

    if (bid < 256) {
        // ------------------------- conv1 -------------------------
        float* AsB  = (float*)SRAW;
        float* BsB  = (float*)(SRAW + 2 * AS_BUF_BYTES);
        float* sh_s = (float*)(SRAW + PIPE_BYTES);   // 64 floats

        const int lane = t & 31;
        const int g    = lane >> 2;
        const int tg   = lane & 3;
        const int warp = t >> 5;
        const int cw   = (warp >> 1) * 32;
        const int nw   = (warp & 1) * 64;

        const int n0  = (bid & 31) * 128;
        const int co0 = ((bid >> 5) & 3) * 64;
        const int bb  = bid >> 7;

        if (t < 64) {
            int co = co0 + t;
            sh_s[t] = b1[co] - m1[co] * (g1[co] * rsqrtf(v1[co] + 1e-5f));
        }

        const float* xb = x1 + (size_t)bb * CINV * N1V;

        MMA_MAINLOOP(g_WT1, xb, N1V, (CINV / 16))

        // epilogue: relu(acc + shift) -> h1T[b][n][co]  (scalar, sector-coalesced)
        #pragma unroll
        for (int cf = 0; cf < 2; cf++) {
            #pragma unroll
            for (int r = 0; r < 2; r++) {
                const int col = cw + cf * 16 + g + r * 8;
                const float sh = sh_s[col];
                const int co = co0 + col;
                #pragma unroll
                for (int nf = 0; nf < 8; nf++) {
                    const int n = n0 + nw + nf * 8 + 2 * tg;
                    float* dst = &g_h1T[((size_t)bb * N1V + n) * COUTV + co];
                    dst[0]     = fmaxf(acc[cf][nf][r * 2 + 0] + sh, 0.f);
                    dst[COUTV] = fmaxf(acc[cf][nf][r * 2 + 1] + sh, 0.f);
                }
            }
        }
    } else {
        // ------------------------- knn (p1 tiled 2x2048 = 32KB) ------------
        float4* p1s = (float4*)SRAW;
        const int kbid = bid - 256;
        const int bb   = kbid >> 7;
        const int n2   = (kbid & 127) * 128 + t;

        const float* q = p2 + ((size_t)bb * N2V + n2) * 3;
        float qx = q[0], qy = q[1], qz = q[2];
        float q2 = fmaf(qx, qx, fmaf(qy, qy, qz * qz));
        float mx = -2.f * qx, my = -2.f * qy, mz = -2.f * qz;

        float s0 = 3.4e38f, s1 = 3.4e38f, s2 = 3.4e38f;
        int   i0 = 0,       i1 = 0,       i2 = 0;

        const float* p1b = p1 + (size_t)bb * N1V * 3;
        for (int tile = 0; tile < 2; tile++) {
            __syncthreads();
            const float* pt = p1b + tile * 2048 * 3;
            for (int e = t; e < 2048; e += 128) {
                float x = pt[e * 3 + 0], y = pt[e * 3 + 1], z = pt[e * 3 + 2];
                p1s[e] = make_float4(x, y, z, fmaf(x, x, fmaf(y, y, z * z)));
            }
            __syncthreads();
            const int jbase = tile * 2048;
            #pragma unroll 4
            for (int j = 0; j < 2048; j++) {
                float4 f = p1s[j];
                float s = fmaf(mx, f.x, f.w);
                s = fmaf(my, f.y, s);
                s = fmaf(mz, f.z, s);
                if (s < s2) {
                    int jj = jbase + j;
                    if (s < s1) {
                        s2 = s1; i2 = i1;
                        if (s < s0) { s1 = s0; i1 = i0; s0 = s; i0 = jj; }
                        else        { s1 = s;  i1 = jj; }
                    } else { s2 = s; i2 = jj; }
                }
            }
        }

        float r0 = 1.f / (s0 + q2 + 1e-8f);
        float r1 = 1.f / (s1 + q2 + 1e-8f);
        float r2 = 1.f / (s2 + q2 + 1e-8f);
        float inv = 1.f / (r0 + r1 + r2);

        int base = (bb * N2V + n2) * 3;
        g_idx[base + 0] = i0; g_idx[base + 1] = i1; g_idx[base + 2] = i2;
        g_wgt[base + 0] = r0 * inv; g_wgt[base + 1] = r1 * inv; g_wgt[base + 2] = r2 * inv;
    }
}

// ---------------------------------------------------------------------------
// conv2: y = relu(tf32 GEMM + shift) + 3-NN weighted gather of h1T.
// One launch per batch (bb passed as param) so ncu's fixed capture index
// lands on this kernel. Acc staged through smem; float4 gather+store.
// ---------------------------------------------------------------------------
#define STAGE_STRIDE 136
__global__ __launch_bounds__(128, 4)
void conv2_kernel(const float* __restrict__ x2,
                  const float* __restrict__ b2, const float* __restrict__ m2,
                  const float* __restrict__ g2, const float* __restrict__ v2,
                  float* __restrict__ yout, int bb)
{
    extern __shared__ char SRAW[];
    float* AsB   = (float*)SRAW;
    float* BsB   = (float*)(SRAW + 2 * AS_BUF_BYTES);
    float* stage = (float*)SRAW;                    // reused after mainloop
    int*   idx_s = (int*)(SRAW + 34816);
    float* w_s   = (float*)(SRAW + 36352);
    float* sh_s  = (float*)(SRAW + 37888);

    const int t  = threadIdx.x;
    const int lane = t & 31;
    const int g    = lane >> 2;
    const int tg   = lane & 3;
    const int warp = t >> 5;
    const int cw   = (warp >> 1) * 32;
    const int nw   = (warp & 1) * 64;

    const int n0  = blockIdx.x * 128;
    const int co0 = blockIdx.y * 64;

    if (t < 64) {
        int co = co0 + t;
        sh_s[t] = b2[co] - m2[co] * (g2[co] * rsqrtf(v2[co] + 1e-5f));
    }
    {
        int base = (bb * N2V + n0) * 3;
        for (int u = t; u < 384; u += 128) {
            idx_s[u] = g_idx[base + u];
            w_s[u]   = g_wgt[base + u];
        }
    }

    const float* xb = x2 + (size_t)bb * CSKV * N2V;

    MMA_MAINLOOP(g_WT2, xb, N2V, (CSKV / 16))

    // stage raw acc -> smem [co_local][n_local] (float2 stores)
    #pragma unroll
    for (int cf = 0; cf < 2; cf++) {
        #pragma unroll
        for (int r = 0; r < 2; r++) {
            const int col = cw + cf * 16 + g + r * 8;
            #pragma unroll
            for (int nf = 0; nf < 8; nf++) {
                const int nl = nw + nf * 8 + 2 * tg;
                *(float2*)&stage[col * STAGE_STRIDE + nl] =
                    make_float2(acc[cf][nf][r * 2], acc[cf][nf][r * 2 + 1]);
            }
        }
    }
    __syncthreads();

    // epilogue in 8co x 8n per-thread pattern
    const int tx = t & 15;
    const int ty = t >> 4;

    float r_[8][8];
    #pragma unroll
    for (int i = 0; i < 8; i++) {
        const float sh = sh_s[ty * 8 + i];
        float4 vA = *(const float4*)&stage[(ty * 8 + i) * STAGE_STRIDE + tx * 8];
        float4 vB = *(const float4*)&stage[(ty * 8 + i) * STAGE_STRIDE + tx * 8 + 4];
        r_[i][0] = fmaxf(vA.x + sh, 0.f);
        r_[i][1] = fmaxf(vA.y + sh, 0.f);
        r_[i][2] = fmaxf(vA.z + sh, 0.f);
        r_[i][3] = fmaxf(vA.w + sh, 0.f);
        r_[i][4] = fmaxf(vB.x + sh, 0.f);
        r_[i][5] = fmaxf(vB.y + sh, 0.f);
        r_[i][6] = fmaxf(vB.z + sh, 0.f);
        r_[i][7] = fmaxf(vB.w + sh, 0.f);
    }

    #pragma unroll
    for (int j = 0; j < 8; j++) {
        int cj = tx * 8 + j;
        #pragma unroll
        for (int k = 0; k < 3; k++) {
            int   id = idx_s[cj * 3 + k];
            float w  = w_s[cj * 3 + k];
            const float* src = &g_h1T[((size_t)bb * N1V + id) * COUTV + co0 + ty * 8];
            float4 gA = *(const float4*)&src[0];
            float4 gB = *(const float4*)&src[4];
            r_[0][j] = fmaf(w, gA.x, r_[0][j]);
            r_[1][j] = fmaf(w, gA.y, r_[1][j]);
            r_[2][j] = fmaf(w, gA.z, r_[2][j]);
            r_[3][j] = fmaf(w, gA.w, r_[3][j]);
            r_[4][j] = fmaf(w, gB.x, r_[4][j]);
            r_[5][j] = fmaf(w, gB.y, r_[5][j]);
            r_[6][j] = fmaf(w, gB.z, r_[6][j]);
            r_[7][j] = fmaf(w, gB.w, r_[7][j]);
        }
    }

    #pragma unroll
    for (int i = 0; i < 8; i++) {
        int co = co0 + ty * 8 + i;
        float* drow = &yout[((size_t)(bb * COUTV + co)) * N2V + n0 + tx * 8];
        *(float4*)&drow[0] = make_float4(r_[i][0], r_[i][1], r_[i][2], r_[i][3]);
        *(float4*)&drow[4] = make_float4(r_[i][4], r_[i][5], r_[i][6], r_[i][7]);
    }
}

// ---------------------------------------------------------------------------
extern "C" void kernel_launch(void* const* d_in, const int* in_sizes, int n_in,
                              void* d_out, int out_size)
{
    const float* p1 = (const float*)d_in[0];
    const float* x1 = (const float*)d_in[1];
    const float* p2 = (const float*)d_in[2];
    const float* x2 = (const float*)d_in[3];
    const float* W1 = (const float*)d_in[4];
    const float* g1 = (const float*)d_in[5];
    const float* b1 = (const float*)d_in[6];
    const float* m1 = (const float*)d_in[7];
    const float* v1 = (const float*)d_in[8];
    const float* W2 = (const float*)d_in[9];
    const float* g2 = (const float*)d_in[10];
    const float* b2 = (const float*)d_in[11];
    const float* m2 = (const float*)d_in[12];
    const float* v2 = (const float*)d_in[13];

    float* out = (float*)d_out;
    const int P2SZ = NB * N2V * 3;
    const int YSZ  = NB * COUTV * N2V;

    float* yout = out;
    if (out_size == P2SZ + YSZ) {
        cudaMemcpyAsync(out, p2, (size_t)P2SZ * sizeof(float),
                        cudaMemcpyDeviceToDevice);
        yout = out + P2SZ;
    }

    cudaFuncSetAttribute(front_kernel,
                         cudaFuncAttributeMaxDynamicSharedMemorySize, 32768);
    cudaFuncSetAttribute(conv2_kernel,
                         cudaFuncAttributeMaxDynamicSharedMemorySize, 38400);

    wtrans_kernel<<<dim3(COUTV / 32, CINV / 32, 2), 256>>>(W1, g1, v1, W2, g2, v2);
    front_kernel<<<512, 128, 32768>>>(x1, b1, m1, g1, v1, p1, p2);
    conv2_kernel<<<dim3(N2V / 128, COUTV / 64), 128, 38400>>>(
        x2, b2, m2, g2, v2, yout, 0);
    conv2_kernel<<<dim3(N2V / 128, COUTV / 64), 128, 38400>>>(
        x2, b2, m2, g2, v2, yout, 1);
}

// round 14
// speedup vs baseline: 1.1590x; 1.1590x over previous
#include <cuda_runtime.h>
#include <cstdint>

#define NB    2
#define N1V   4096
#define N2V   16384
#define CINV  512
#define CSKV  256
#define COUTV 256

#define AS_STRIDE 72    // words; (8*tg+g)%32 distinct -> conflict-free frags
#define BS_STRIDE 136
#define AS_BUF_BYTES (16 * AS_STRIDE * 4)   // 4608
#define BS_BUF_BYTES (16 * BS_STRIDE * 4)   // 8704
#define PIPE_BYTES   (2 * AS_BUF_BYTES + 2 * BS_BUF_BYTES)  // 26624

// Scratch: h1 transposed [b][n1][co], knn idx/weights, tf32 weights WT[k][co].
__device__ float g_h1T[(size_t)NB * N1V * COUTV];
__device__ int   g_idx[NB * N2V * 3];
__device__ float g_wgt[NB * N2V * 3];
__device__ float g_WT1[CINV * COUTV];
__device__ float g_WT2[CSKV * COUTV];

// ---------------- helpers ----------------
__device__ __forceinline__ uint32_t s2u(const void* p) {
    return (uint32_t)__cvta_generic_to_shared(p);
}
__device__ __forceinline__ void cpa16(uint32_t dst, const void* src) {
    asm volatile("cp.async.cg.shared.global [%0], [%1], 16;\n" :: "r"(dst), "l"(src));
}
__device__ __forceinline__ void cpa_commit() {
    asm volatile("cp.async.commit_group;\n");
}
__device__ __forceinline__ void cpa_wait1() {
    asm volatile("cp.async.wait_group 1;\n");
}
__device__ __forceinline__ void cpa_wait0() {
    asm volatile("cp.async.wait_group 0;\n");
}
__device__ __forceinline__ uint32_t f2tf32(float x) {
    uint32_t u;
    asm("cvt.rna.tf32.f32 %0, %1;" : "=r"(u) : "f"(x));
    return u;
}
__device__ __forceinline__ void mma_tf32(float* c, const uint32_t* a,
                                         uint32_t b0, uint32_t b1) {
    asm volatile(
        "mma.sync.aligned.m16n8k8.row.col.f32.tf32.tf32.f32 "
        "{%0,%1,%2,%3}, {%4,%5,%6,%7}, {%8,%9}, {%0,%1,%2,%3};\n"
        : "+f"(c[0]), "+f"(c[1]), "+f"(c[2]), "+f"(c[3])
        : "r"(a[0]), "r"(a[1]), "r"(a[2]), "r"(a[3]), "r"(b0), "r"(b1));
}

// ===========================================================================
// Prologue: WT[k][co] = tf32_round( W[co][k] * bn_scale[co] )
// ===========================================================================
__global__ __launch_bounds__(256)
void wtrans_kernel(const float* __restrict__ W1, const float* __restrict__ g1,
                   const float* __restrict__ v1,
                   const float* __restrict__ W2, const float* __restrict__ g2,
                   const float* __restrict__ v2)
{
    __shared__ float tile[32][33];
    const int which = blockIdx.z;
    const int Cin   = which ? CSKV : CINV;
    if (blockIdx.y * 32 >= Cin) return;
    const float* W  = which ? W2 : W1;
    const float* g  = which ? g2 : g1;
    const float* v  = which ? v2 : v1;
    float* WT       = which ? g_WT2 : g_WT1;

    const int co0 = blockIdx.x * 32;
    const int k0  = blockIdx.y * 32;
    const int lx  = threadIdx.x & 31;
    const int ly  = threadIdx.x >> 5;

    #pragma unroll
    for (int r = 0; r < 4; r++)
        tile[ly + r * 8][lx] = W[(size_t)(co0 + ly + r * 8) * Cin + k0 + lx];
    __syncthreads();

    const float sc = g[co0 + lx] * rsqrtf(v[co0 + lx] + 1e-5f);
    #pragma unroll
    for (int r = 0; r < 4; r++)
        WT[(size_t)(k0 + ly + r * 8) * COUTV + co0 + lx] =
            __uint_as_float(f2tf32(tile[lx][ly + r * 8] * sc));
}

// ===========================================================================
// tf32 MMA mainloop: tile 64co x 128n x 16k, 128 thr (4 warps, 2co x 2n),
// warp tile 32co x 64n (2 x 8 m16n8k8 frags). Double-buffered cp.async.
// acc[2][8][4]; thread element map:
//   co = cw + cf*16 + g + (e>=2? 8:0),  n = nw + nf*8 + 2*tg + (e&1)
// ===========================================================================
#define MMA_MAINLOOP(WTSRC, XB, NSTRIDE, NCHUNKS)                                \
    const int a_row = t >> 4, a_c4 = (t & 15) * 4;                               \
    const uint32_t sA0 = s2u(AsB) + (uint32_t)(a_row * AS_STRIDE + a_c4) * 4u;   \
    const uint32_t sA1 = s2u(AsB) + (uint32_t)((a_row + 8) * AS_STRIDE + a_c4) * 4u; \
    const int b_col = (t & 31) * 4;                                              \
    const int b_rw  = t >> 5;                                                    \
    uint32_t sB[4];                                                              \
    _Pragma("unroll")                                                            \
    for (int r = 0; r < 4; r++)                                                  \
        sB[r] = s2u(BsB) + (uint32_t)((b_rw + r * 4) * BS_STRIDE + b_col) * 4u;  \
    float acc[2][8][4];                                                          \
    _Pragma("unroll")                                                            \
    for (int cf = 0; cf < 2; cf++)                                               \
        _Pragma("unroll")                                                        \
        for (int nf = 0; nf < 8; nf++)                                           \
            _Pragma("unroll")                                                    \
            for (int e = 0; e < 4; e++) acc[cf][nf][e] = 0.f;                    \
    cpa16(sA0, &WTSRC[(size_t)a_row * COUTV + co0 + a_c4]);                      \
    cpa16(sA1, &WTSRC[(size_t)(a_row + 8) * COUTV + co0 + a_c4]);                \
    _Pragma("unroll")                                                            \
    for (int r = 0; r < 4; r++)                                                  \
        cpa16(sB[r], &XB[(size_t)(b_rw + r * 4) * NSTRIDE + n0 + b_col]);        \
    cpa_commit();                                                                \
    for (int ch = 0; ch < NCHUNKS; ch++) {                                       \
        const int cur = ch & 1;                                                  \
        if (ch + 1 < NCHUNKS) {                                                  \
            const int nxt = cur ^ 1;                                             \
            const int k0n = (ch + 1) * 16;                                       \
            cpa16(sA0 + nxt * AS_BUF_BYTES,                                      \
                  &WTSRC[(size_t)(k0n + a_row) * COUTV + co0 + a_c4]);           \
            cpa16(sA1 + nxt * AS_BUF_BYTES,                                      \
                  &WTSRC[(size_t)(k0n + a_row + 8) * COUTV + co0 + a_c4]);       \
            _Pragma("unroll")                                                    \
            for (int r = 0; r < 4; r++)                                          \
                cpa16(sB[r] + nxt * BS_BUF_BYTES,                                \
                      &XB[(size_t)(k0n + b_rw + r * 4) * NSTRIDE + n0 + b_col]); \
            cpa_commit();                                                        \
            cpa_wait1();                                                         \
        } else {                                                                 \
            cpa_wait0();                                                         \
        }                                                                        \
        __syncthreads();                                                         \
        const float* Ab = AsB + cur * (16 * AS_STRIDE);                          \
        const float* Bb = BsB + cur * (16 * BS_STRIDE);                          \
        _Pragma("unroll")                                                        \
        for (int s = 0; s < 2; s++) {                                            \
            const int kr0 = s * 8 + tg;                                          \
            uint32_t af[2][4];                                                   \
            _Pragma("unroll")                                                    \
            for (int cf = 0; cf < 2; cf++) {                                     \
                const int cb = cw + cf * 16 + g;                                 \
                af[cf][0] = __float_as_uint(Ab[kr0 * AS_STRIDE + cb]);           \
                af[cf][1] = __float_as_uint(Ab[kr0 * AS_STRIDE + cb + 8]);       \
                af[cf][2] = __float_as_uint(Ab[(kr0 + 4) * AS_STRIDE + cb]);     \
                af[cf][3] = __float_as_uint(Ab[(kr0 + 4) * AS_STRIDE + cb + 8]); \
            }                                                                    \
            _Pragma("unroll")                                                    \
            for (int nf = 0; nf < 8; nf++) {                                     \
                const int nn = nw + nf * 8 + g;                                  \
                uint32_t b0 = f2tf32(Bb[kr0 * BS_STRIDE + nn]);                  \
                uint32_t b1 = f2tf32(Bb[(kr0 + 4) * BS_STRIDE + nn]);            \
                mma_tf32(acc[0][nf], af[0], b0, b1);                             \
                mma_tf32(acc[1][nf], af[1], b0, b1);                             \
            }                                                                    \
        }                                                                        \
        __syncthreads();                                                         \
    }

// ---------------------------------------------------------------------------
// Fused front kernel: blocks [0,256) conv1 (tf32 MMA), blocks [256,512) 3-NN.
// knn uses an 8-point FMIN prefilter: the top-3 insert branch runs only when
// min(8 candidate scores) beats the current 3rd-best.
// ---------------------------------------------------------------------------
__global__ __launch_bounds__(128, 4)
void front_kernel(const float* __restrict__ x1,
                  const float* __restrict__ b1, const float* __restrict__ m1,
                  const float* __restrict__ g1, const float* __restrict__ v1,
                  const float* __restrict__ p1, const float* __restrict__ p2)
{
    extern __shared__ char SRAW[];
    const int t   = threadIdx.x;
    const int bid = blockIdx.x;

    if (bid < 256) {
        // ------------------------- conv1 -------------------------
        float* AsB  = (float*)SRAW;
        float* BsB  = (float*)(SRAW + 2 * AS_BUF_BYTES);
        float* sh_s = (float*)(SRAW + PIPE_BYTES);   // 64 floats

        const int lane = t & 31;
        const int g    = lane >> 2;
        const int tg   = lane & 3;
        const int warp = t >> 5;
        const int cw   = (warp >> 1) * 32;
        const int nw   = (warp & 1) * 64;

        const int n0  = (bid & 31) * 128;
        const int co0 = ((bid >> 5) & 3) * 64;
        const int bb  = bid >> 7;

        if (t < 64) {
            int co = co0 + t;
            sh_s[t] = b1[co] - m1[co] * (g1[co] * rsqrtf(v1[co] + 1e-5f));
        }

        const float* xb = x1 + (size_t)bb * CINV * N1V;

        MMA_MAINLOOP(g_WT1, xb, N1V, (CINV / 16))

        // epilogue: relu(acc + shift) -> h1T[b][n][co]
        #pragma unroll
        for (int cf = 0; cf < 2; cf++) {
            #pragma unroll
            for (int r = 0; r < 2; r++) {
                const int col = cw + cf * 16 + g + r * 8;
                const float sh = sh_s[col];
                const int co = co0 + col;
                #pragma unroll
                for (int nf = 0; nf < 8; nf++) {
                    const int n = n0 + nw + nf * 8 + 2 * tg;
                    float* dst = &g_h1T[((size_t)bb * N1V + n) * COUTV + co];
                    dst[0]     = fmaxf(acc[cf][nf][r * 2 + 0] + sh, 0.f);
                    dst[COUTV] = fmaxf(acc[cf][nf][r * 2 + 1] + sh, 0.f);
                }
            }
        }
    } else {
        // ------------------------- knn (p1 tiled 2x2048 = 32KB) ------------
        float4* p1s = (float4*)SRAW;
        const int kbid = bid - 256;
        const int bb   = kbid >> 7;
        const int n2   = (kbid & 127) * 128 + t;

        const float* q = p2 + ((size_t)bb * N2V + n2) * 3;
        float qx = q[0], qy = q[1], qz = q[2];
        float q2 = fmaf(qx, qx, fmaf(qy, qy, qz * qz));
        float mx = -2.f * qx, my = -2.f * qy, mz = -2.f * qz;

        float s0 = 3.4e38f, s1 = 3.4e38f, s2 = 3.4e38f;
        int   i0 = 0,       i1 = 0,       i2 = 0;

        const float* p1b = p1 + (size_t)bb * N1V * 3;
        for (int tile = 0; tile < 2; tile++) {
            __syncthreads();
            const float* pt = p1b + tile * 2048 * 3;
            for (int e = t; e < 2048; e += 128) {
                float x = pt[e * 3 + 0], y = pt[e * 3 + 1], z = pt[e * 3 + 2];
                p1s[e] = make_float4(x, y, z, fmaf(x, x, fmaf(y, y, z * z)));
            }
            __syncthreads();
            const int jbase = tile * 2048;

            for (int j0 = 0; j0 < 2048; j0 += 8) {
                float sv[8];
                #pragma unroll
                for (int u = 0; u < 8; u++) {
                    float4 f = p1s[j0 + u];
                    float s = fmaf(mx, f.x, f.w);
                    s = fmaf(my, f.y, s);
                    sv[u] = fmaf(mz, f.z, s);
                }
                float m01 = fminf(sv[0], sv[1]);
                float m23 = fminf(sv[2], sv[3]);
                float m45 = fminf(sv[4], sv[5]);
                float m67 = fminf(sv[6], sv[7]);
                float m = fminf(fminf(m01, m23), fminf(m45, m67));

                if (m < s2) {
                    #pragma unroll
                    for (int u = 0; u < 8; u++) {
                        float s = sv[u];
                        if (s < s2) {
                            int jj = jbase + j0 + u;
                            if (s < s1) {
                                s2 = s1; i2 = i1;
                                if (s < s0) { s1 = s0; i1 = i0; s0 = s; i0 = jj; }
                                else        { s1 = s;  i1 = jj; }
                            } else { s2 = s; i2 = jj; }
                        }
                    }
                }
            }
        }

        float r0 = 1.f / (s0 + q2 + 1e-8f);
        float r1 = 1.f / (s1 + q2 + 1e-8f);
        float r2 = 1.f / (s2 + q2 + 1e-8f);
        float inv = 1.f / (r0 + r1 + r2);

        int base = (bb * N2V + n2) * 3;
        g_idx[base + 0] = i0; g_idx[base + 1] = i1; g_idx[base + 2] = i2;
        g_wgt[base + 0] = r0 * inv; g_wgt[base + 1] = r1 * inv; g_wgt[base + 2] = r2 * inv;
    }
}

// ---------------------------------------------------------------------------
// conv2: y = relu(tf32 GEMM + shift) + 3-NN weighted gather of h1T.
// Single launch, grid (N2V/128, COUTV/64, NB). Acc staged through smem.
// ---------------------------------------------------------------------------
#define STAGE_STRIDE 136
__global__ __launch_bounds__(128, 4)
void conv2_kernel(const float* __restrict__ x2,
                  const float* __restrict__ b2, const float* __restrict__ m2,
                  const float* __restrict__ g2, const float* __restrict__ v2,
                  float* __restrict__ yout)
{
    extern __shared__ char SRAW[];
    float* AsB   = (float*)SRAW;
    float* BsB   = (float*)(SRAW + 2 * AS_BUF_BYTES);
    float* stage = (float*)SRAW;                    // reused after mainloop
    int*   idx_s = (int*)(SRAW + 34816);
    float* w_s   = (float*)(SRAW + 36352);
    float* sh_s  = (float*)(SRAW + 37888);

    const int t  = threadIdx.x;
    const int lane = t & 31;
    const int g    = lane >> 2;
    const int tg   = lane & 3;
    const int warp = t >> 5;
    const int cw   = (warp >> 1) * 32;
    const int nw   = (warp & 1) * 64;

    const int n0  = blockIdx.x * 128;
    const int co0 = blockIdx.y * 64;
    const int bb  = blockIdx.z;

    if (t < 64) {
        int co = co0 + t;
        sh_s[t] = b2[co] - m2[co] * (g2[co] * rsqrtf(v2[co] + 1e-5f));
    }
    {
        int base = (bb * N2V + n0) * 3;
        for (int u = t; u < 384; u += 128) {
            idx_s[u] = g_idx[base + u];
            w_s[u]   = g_wgt[base + u];
        }
    }

    const float* xb = x2 + (size_t)bb * CSKV * N2V;

    MMA_MAINLOOP(g_WT2, xb, N2V, (CSKV / 16))

    // stage raw acc -> smem [co_local][n_local] (float2 stores)
    #pragma unroll
    for (int cf = 0; cf < 2; cf++) {
        #pragma unroll
        for (int r = 0; r < 2; r++) {
            const int col = cw + cf * 16 + g + r * 8;
            #pragma unroll
            for (int nf = 0; nf < 8; nf++) {
                const int nl = nw + nf * 8 + 2 * tg;
                *(float2*)&stage[col * STAGE_STRIDE + nl] =
                    make_float2(acc[cf][nf][r * 2], acc[cf][nf][r * 2 + 1]);
            }
        }
    }
    __syncthreads();

    // epilogue in 8co x 8n per-thread pattern
    const int tx = t & 15;
    const int ty = t >> 4;

    float r_[8][8];
    #pragma unroll
    for (int i = 0; i < 8; i++) {
        const float sh = sh_s[ty * 8 + i];
        float4 vA = *(const float4*)&stage[(ty * 8 + i) * STAGE_STRIDE + tx * 8];
        float4 vB = *(const float4*)&stage[(ty * 8 + i) * STAGE_STRIDE + tx * 8 + 4];
        r_[i][0] = fmaxf(vA.x + sh, 0.f);
        r_[i][1] = fmaxf(vA.y + sh, 0.f);
        r_[i][2] = fmaxf(vA.z + sh, 0.f);
        r_[i][3] = fmaxf(vA.w + sh, 0.f);
        r_[i][4] = fmaxf(vB.x + sh, 0.f);
        r_[i][5] = fmaxf(vB.y + sh, 0.f);
        r_[i][6] = fmaxf(vB.z + sh, 0.f);
        r_[i][7] = fmaxf(vB.w + sh, 0.f);
    }

    #pragma unroll
    for (int j = 0; j < 8; j++) {
        int cj = tx * 8 + j;
        #pragma unroll
        for (int k = 0; k < 3; k++) {
            int   id = idx_s[cj * 3 + k];
            float w  = w_s[cj * 3 + k];
            const float* src = &g_h1T[((size_t)bb * N1V + id) * COUTV + co0 + ty * 8];
            float4 gA = *(const float4*)&src[0];
            float4 gB = *(const float4*)&src[4];
            r_[0][j] = fmaf(w, gA.x, r_[0][j]);
            r_[1][j] = fmaf(w, gA.y, r_[1][j]);
            r_[2][j] = fmaf(w, gA.z, r_[2][j]);
            r_[3][j] = fmaf(w, gA.w, r_[3][j]);
            r_[4][j] = fmaf(w, gB.x, r_[4][j]);
            r_[5][j] = fmaf(w, gB.y, r_[5][j]);
            r_[6][j] = fmaf(w, gB.z, r_[6][j]);
            r_[7][j] = fmaf(w, gB.w, r_[7][j]);
        }
    }

    #pragma unroll
    for (int i = 0; i < 8; i++) {
        int co = co0 + ty * 8 + i;
        float* drow = &yout[((size_t)(bb * COUTV + co)) * N2V + n0 + tx * 8];
        *(float4*)&drow[0] = make_float4(r_[i][0], r_[i][1], r_[i][2], r_[i][3]);
        *(float4*)&drow[4] = make_float4(r_[i][4], r_[i][5], r_[i][6], r_[i][7]);
    }
}

// ---------------------------------------------------------------------------
extern "C" void kernel_launch(void* const* d_in, const int* in_sizes, int n_in,
                              void* d_out, int out_size)
{
    const float* p1 = (const float*)d_in[0];
    const float* x1 = (const float*)d_in[1];
    const float* p2 = (const float*)d_in[2];
    const float* x2 = (const float*)d_in[3];
    const float* W1 = (const float*)d_in[4];
    const float* g1 = (const float*)d_in[5];
    const float* b1 = (const float*)d_in[6];
    const float* m1 = (const float*)d_in[7];
    const float* v1 = (const float*)d_in[8];
    const float* W2 = (const float*)d_in[9];
    const float* g2 = (const float*)d_in[10];
    const float* b2 = (const float*)d_in[11];
    const float* m2 = (const float*)d_in[12];
    const float* v2 = (const float*)d_in[13];

    float* out = (float*)d_out;
    const int P2SZ = NB * N2V * 3;
    const int YSZ  = NB * COUTV * N2V;

    float* yout = out;
    if (out_size == P2SZ + YSZ) {
        cudaMemcpyAsync(out, p2, (size_t)P2SZ * sizeof(float),
                        cudaMemcpyDeviceToDevice);
        yout = out + P2SZ;
    }

    cudaFuncSetAttribute(front_kernel,
                         cudaFuncAttributeMaxDynamicSharedMemorySize, 32768);
    cudaFuncSetAttribute(conv2_kernel,
                         cudaFuncAttributeMaxDynamicSharedMemorySize, 38400);

    wtrans_kernel<<<dim3(COUTV / 32, CINV / 32, 2), 256>>>(W1, g1, v1, W2, g2, v2);
    front_kernel<<<512, 128, 32768>>>(x1, b1, m1, g1, v1, p1, p2);
    conv2_kernel<<<dim3(N2V / 128, COUTV / 64, NB), 128, 38400>>>(
        x2, b2, m2, g2, v2, yout);
}